// round 11
// baseline (speedup 1.0000x reference)
#include <cuda_runtime.h>
#include <cuda_bf16.h>
#include <math.h>
#include <stdint.h>

#define DIMN 64
#define HID 32
#define BATCH 1024
#define DH 2048   // DIMN*HID
#define LOG2PI_F 1.8378770664093453f

// ---------------- scratch (device globals; no allocation allowed) ----------------
// g_w1h/g_w1l rely on static zero-init for the masked region (prep1 writes only j < dhi).
__device__ float g_wn0[3 * (size_t)DH * DIMN];
__device__ float g_wn2[3 * (size_t)DIMN * DH];
__device__ __nv_bfloat16 g_w1h[3 * (size_t)DH * DH];
__device__ __nv_bfloat16 g_w1l[3 * (size_t)DH * DH];
__device__ float g_w1d[3 * 64 * 32 * 32];   // compact f32 diag blocks of wn1
__device__ float g_v0c[3 * 64 * 32];        // compact diag column of wn0
__device__ float g_w2c[3 * 64 * 32];        // compact diag row of wn2
__device__ __nv_bfloat16 g_t1h[(size_t)BATCH * DH];
__device__ __nv_bfloat16 g_t1l[(size_t)BATCH * DH];
__device__ float g_t2[BATCH*DH];
__device__ float g_part[8 * BATCH * DIMN];
__device__ float g_ldjc[BATCH * DIMN];
__device__ float g_xa[BATCH*DIMN];
__device__ float g_xb[BATCH*DIMN];
__device__ float g_ldj[BATCH];

struct PtrSet { const float* W[3]; const float* dw[3]; };

// ---------------- helpers ----------------
__device__ __forceinline__ uint32_t smem_u32(const void* p) {
    uint32_t a;
    asm("{ .reg .u64 t; cvta.to.shared.u64 t, %1; cvt.u32.u64 %0, t; }" : "=r"(a) : "l"(p));
    return a;
}
__device__ __forceinline__ void cp_async16(uint32_t dst, const void* src) {
    asm volatile("cp.async.cg.shared.global [%0], [%1], 16;" :: "r"(dst), "l"(src) : "memory");
}
__device__ __forceinline__ void cp_commit() {
    asm volatile("cp.async.commit_group;" ::: "memory");
}
#define CP_WAIT(n) asm volatile("cp.async.wait_group %0;" :: "n"(n) : "memory")

#define LDSM4(r, a) \
    asm volatile("ldmatrix.sync.aligned.m8n8.x4.shared.b16 {%0,%1,%2,%3}, [%4];" \
        : "=r"((r)[0]), "=r"((r)[1]), "=r"((r)[2]), "=r"((r)[3]) : "r"(a))

__device__ __forceinline__ void mma_bf16(float* c, const uint32_t* a, const uint32_t* b) {
    asm volatile("mma.sync.aligned.m16n8k16.row.col.f32.bf16.bf16.f32 "
                 "{%0,%1,%2,%3}, {%4,%5,%6,%7}, {%8,%9}, {%0,%1,%2,%3};"
                 : "+f"(c[0]), "+f"(c[1]), "+f"(c[2]), "+f"(c[3])
                 : "r"(a[0]), "r"(a[1]), "r"(a[2]), "r"(a[3]), "r"(b[0]), "r"(b[1]));
}
__device__ __forceinline__ void split_bf16(float v, __nv_bfloat16& h, __nv_bfloat16& l) {
    h = __float2bfloat16(v);
    l = __float2bfloat16(v - __bfloat162float(h));
}

// ---------------- prep0 (W0: 2048x64), warp-per-row, fused over 3 flows ---------------
__global__ void __launch_bounds__(256)
prep0_fused(PtrSet ps, float* __restrict__ wn0_base, float* __restrict__ v0c_base) {
    const int f = blockIdx.y;
    const int o = blockIdx.x * 8 + (threadIdx.x >> 5);   // row 0..2047
    const int lane = threadIdx.x & 31;
    const int bi = o >> 5;                               // diag col index (ib=1)
    const float* Wr = ps.W[f] + (size_t)o * DIMN;
    float* wn = wn0_base + (size_t)f * DH * DIMN + (size_t)o * DIMN;

    const int j0 = lane, j1 = lane + 32;
    float v0 = Wr[j0], v1 = Wr[j1];
    float w0 = (j0 > bi) ? 0.f : ((j0 == bi) ? expf(v0) : v0);
    float w1 = (j1 > bi) ? 0.f : ((j1 == bi) ? expf(v1) : v1);
    float ss = w0 * w0 + w1 * w1;
    #pragma unroll
    for (int off = 16; off; off >>= 1) ss += __shfl_xor_sync(0xffffffffu, ss, off);
    const float scale = expf(ps.dw[f][o]) / sqrtf(ss);
    wn[j0] = w0 * scale;
    wn[j1] = w1 * scale;
    if (j0 == bi) v0c_base[f * 2048 + o] = w0 * scale;
    if (j1 == bi) v0c_base[f * 2048 + o] = w1 * scale;
}

// ---------------- prep1 (W1: 2048x2048) -> bf16 hi/lo + f32 diag, fused --------------
__global__ void prep1_fused(PtrSet ps,
                            __nv_bfloat16* __restrict__ wh_base,
                            __nv_bfloat16* __restrict__ wl_base,
                            float* __restrict__ diag_base) {
    extern __shared__ float sw[];
    __shared__ float red[8];
    const int f = blockIdx.y;
    const int o = blockIdx.x;            // 0..2047
    const int bi = o >> 5, r = o & 31;
    const int dlo = bi * 32, dhi = dlo + 32;
    const float* Wr = ps.W[f] + (size_t)o * DH;
    __nv_bfloat16* wh = wh_base + (size_t)f * DH * DH + (size_t)o * DH;
    __nv_bfloat16* wl = wl_base + (size_t)f * DH * DH + (size_t)o * DH;
    float* diag = diag_base + f * 64 * 1024;

    float ss = 0.f;
    for (int j = threadIdx.x; j < dhi; j += blockDim.x) {
        float Wv = Wr[j];
        float w = (j >= dlo) ? expf(Wv) : Wv;
        sw[j] = w;
        ss += w * w;
    }
    #pragma unroll
    for (int off = 16; off; off >>= 1) ss += __shfl_down_sync(0xffffffffu, ss, off);
    if ((threadIdx.x & 31) == 0) red[threadIdx.x >> 5] = ss;
    __syncthreads();
    if (threadIdx.x == 0) {
        float v = 0.f;
        for (int w = 0; w < 8; w++) v += red[w];
        red[0] = v;
    }
    __syncthreads();
    const float scale = expf(ps.dw[f][o]) / sqrtf(red[0]);
    for (int j = threadIdx.x; j < dhi; j += blockDim.x) {
        float v = sw[j] * scale;
        __nv_bfloat16 h, l;
        split_bf16(v, h, l);
        wh[j] = h;
        wl[j] = l;
    }
    if (threadIdx.x < 32)
        diag[bi * 1024 + r * 32 + threadIdx.x] = sw[dlo + threadIdx.x] * scale;
}

// ---------------- prep2 (W2: 64x2048) -> f32 + compact diag, fused ----------------
__global__ void prep2_fused(PtrSet ps, float* __restrict__ wn2_base,
                            float* __restrict__ w2c_base) {
    extern __shared__ float sw[];
    __shared__ float red[8];
    const int f = blockIdx.y;
    const int o = blockIdx.x;            // 0..63
    const int dlo = o * 32, dhi = dlo + 32;
    const float* Wr = ps.W[f] + (size_t)o * DH;
    float* wn = wn2_base + (size_t)f * DIMN * DH + (size_t)o * DH;

    float ss = 0.f;
    for (int j = threadIdx.x; j < DH; j += blockDim.x) {
        float Wv = Wr[j];
        float w = (j >= dhi) ? 0.f : ((j >= dlo) ? expf(Wv) : Wv);
        sw[j] = w;
        ss += w * w;
    }
    #pragma unroll
    for (int off = 16; off; off >>= 1) ss += __shfl_down_sync(0xffffffffu, ss, off);
    if ((threadIdx.x & 31) == 0) red[threadIdx.x >> 5] = ss;
    __syncthreads();
    if (threadIdx.x == 0) {
        float v = 0.f;
        for (int w = 0; w < 8; w++) v += red[w];
        red[0] = v;
    }
    __syncthreads();
    const float scale = expf(ps.dw[f][o]) / sqrtf(red[0]);
    for (int j = threadIdx.x; j < DH; j += blockDim.x) wn[j] = sw[j] * scale;
    if (threadIdx.x < 32)
        w2c_base[f * 2048 + o * 32 + threadIdx.x] = sw[dlo + threadIdx.x] * scale;
}

// ---------------- layer0 GEMM: t1 = tanh(x @ wn0^T + b0), bf16 hi/lo out ------------
__global__ void __launch_bounds__(256)
gemm_l0(const float* __restrict__ A, const float* __restrict__ Bw,
        const float* __restrict__ bias,
        __nv_bfloat16* __restrict__ Th, __nv_bfloat16* __restrict__ Tl) {
    __shared__ float As[16][68];
    __shared__ float Bs[16][68];
    const int tid  = threadIdx.x;
    const int tcol = tid & 15;
    const int trow = tid >> 4;
    const int m0 = blockIdx.y * 64;
    const int nx = 31 - (int)blockIdx.x;    // longest-first
    const int n0 = nx * 64;
    const int keff = 2 * nx + 2;
    const int nk = (keff + 15) >> 4;        // 1..4

    const int rL = tid >> 2;                // 0..63
    const int kL = (tid & 3) * 4;
    const float* pA = A  + (size_t)(m0 + rL) * DIMN + kL;
    const float* pB = Bw + (size_t)(n0 + rL) * DIMN + kL;

    float acc[4][4];
    #pragma unroll
    for (int i = 0; i < 4; i++)
        #pragma unroll
        for (int j = 0; j < 4; j++) acc[i][j] = 0.f;

    for (int t = 0; t < nk; t++) {
        float4 av = *(const float4*)(pA + t * 16);
        float4 bv = *(const float4*)(pB + t * 16);
        As[kL+0][rL] = av.x; As[kL+1][rL] = av.y; As[kL+2][rL] = av.z; As[kL+3][rL] = av.w;
        Bs[kL+0][rL] = bv.x; Bs[kL+1][rL] = bv.y; Bs[kL+2][rL] = bv.z; Bs[kL+3][rL] = bv.w;
        __syncthreads();
        #pragma unroll
        for (int kk = 0; kk < 16; kk++) {
            float4 a = *(const float4*)&As[kk][trow * 4];
            float4 b = *(const float4*)&Bs[kk][tcol * 4];
            acc[0][0] = fmaf(a.x, b.x, acc[0][0]); acc[0][1] = fmaf(a.x, b.y, acc[0][1]);
            acc[0][2] = fmaf(a.x, b.z, acc[0][2]); acc[0][3] = fmaf(a.x, b.w, acc[0][3]);
            acc[1][0] = fmaf(a.y, b.x, acc[1][0]); acc[1][1] = fmaf(a.y, b.y, acc[1][1]);
            acc[1][2] = fmaf(a.y, b.z, acc[1][2]); acc[1][3] = fmaf(a.y, b.w, acc[1][3]);
            acc[2][0] = fmaf(a.z, b.x, acc[2][0]); acc[2][1] = fmaf(a.z, b.y, acc[2][1]);
            acc[2][2] = fmaf(a.z, b.z, acc[2][2]); acc[2][3] = fmaf(a.z, b.w, acc[2][3]);
            acc[3][0] = fmaf(a.w, b.x, acc[3][0]); acc[3][1] = fmaf(a.w, b.y, acc[3][1]);
            acc[3][2] = fmaf(a.w, b.z, acc[3][2]); acc[3][3] = fmaf(a.w, b.w, acc[3][3]);
        }
        __syncthreads();
    }

    const int ncol = n0 + tcol * 4;
    const float4 bv = *(const float4*)&bias[ncol];
    const float bcol[4] = { bv.x, bv.y, bv.z, bv.w };
    #pragma unroll
    for (int i = 0; i < 4; i++) {
        const int m = m0 + trow * 4 + i;
        __nv_bfloat16 hv[4], lv[4];
        #pragma unroll
        for (int c = 0; c < 4; c++) {
            float tv = tanhf(acc[i][c] + bcol[c]);
            split_bf16(tv, hv[c], lv[c]);
        }
        *(uint2*)&Th[(size_t)m * DH + ncol] = *(uint2*)hv;
        *(uint2*)&Tl[(size_t)m * DH + ncol] = *(uint2*)lv;
    }
}

// ---------------- layer1 HMMA GEMM (split-bf16, block-triangular K-early-exit) ----------
__global__ void __launch_bounds__(256, 2)
gemm_mma_l1(const __nv_bfloat16* __restrict__ Ah, const __nv_bfloat16* __restrict__ Al,
            const __nv_bfloat16* __restrict__ Bh, const __nv_bfloat16* __restrict__ Bl,
            const float* __restrict__ bias, float* __restrict__ T) {
    extern __shared__ char smem[];
    const int K = DH, N = DH;
    const int tid = threadIdx.x, lane = tid & 31, wid = tid >> 5;
    const int warpM = wid & 1, warpN = wid >> 1;   // 2 x 4 warps, warp tile 64x16
    const int bid = blockIdx.x;
    const int jn = 31 - (bid >> 3);
    const int mi = bid & 7;
    const int m0 = mi * 128, n0 = jn * 64;
    const int NK = min(64, 2 * jn + 4);
    const uint32_t sbase = smem_u32(smem);

    const __nv_bfloat16* gA[2] = { Ah + (size_t)m0 * K, Al + (size_t)m0 * K };
    const __nv_bfloat16* gB[2] = { Bh + (size_t)n0 * K, Bl + (size_t)n0 * K };

    float acc[4][2][4];
    #pragma unroll
    for (int i = 0; i < 4; i++)
        #pragma unroll
        for (int j = 0; j < 2; j++)
            #pragma unroll
            for (int e = 0; e < 4; e++) acc[i][j][e] = 0.f;

    const int pr_row = tid >> 2;
    const int pr_ch  = tid & 3;
    #define PREFETCH(t) do {                                                          \
        uint32_t stb = sbase + ((t) % 3) * 24576;                                     \
        _Pragma("unroll")                                                             \
        for (int a = 0; a < 2; a++) {                                                 \
            _Pragma("unroll")                                                         \
            for (int j = 0; j < 2; j++) {                                             \
                int row = pr_row + j * 64;                                            \
                const __nv_bfloat16* src = gA[a] + (size_t)row * K + (t) * 32 + pr_ch * 8; \
                uint32_t dst = stb + a * 8192 + row * 64 + ((pr_ch ^ ((row >> 1) & 3)) * 16); \
                cp_async16(dst, src);                                                 \
            }                                                                         \
            const __nv_bfloat16* srcb = gB[a] + (size_t)pr_row * K + (t) * 32 + pr_ch * 8; \
            uint32_t dstb = stb + 16384 + a * 4096 + pr_row * 64                      \
                          + ((pr_ch ^ ((pr_row >> 1) & 3)) * 16);                     \
            cp_async16(dstb, srcb);                                                   \
        }                                                                             \
        cp_commit();                                                                  \
    } while (0)

    PREFETCH(0);
    PREFETCH(1);

    const int rlA = warpM * 64 + (lane & 15);
    const int rlB = warpN * 16 + (lane & 15);
    const int hi  = lane >> 4;
    const int xA  = (rlA >> 1) & 3;
    const int xB  = (rlB >> 1) & 3;

    for (int t = 0; t < NK; t++) {
        if (t + 1 < NK) { CP_WAIT(1); } else { CP_WAIT(0); }
        __syncthreads();
        if (t + 2 < NK) PREFETCH(t + 2);

        const uint32_t stb = sbase + (t % 3) * 24576;
        const uint32_t pAh = stb + rlA * 64;
        const uint32_t pAl = pAh + 8192;
        const uint32_t pBh = stb + 16384 + rlB * 64;
        const uint32_t pBl = pBh + 4096;

        #pragma unroll
        for (int ks = 0; ks < 2; ks++) {
            const uint32_t cA = (uint32_t)(((ks * 2 + hi) ^ xA) * 16);
            const uint32_t cB = (uint32_t)(((ks * 2 + hi) ^ xB) * 16);
            uint32_t ah[4][4], al[4][4], bh[2][2], bl[2][2];
            #pragma unroll
            for (int mt = 0; mt < 4; mt++) {
                LDSM4(ah[mt], pAh + mt * 1024 + cA);
                LDSM4(al[mt], pAl + mt * 1024 + cA);
            }
            {
                uint32_t r[4];
                LDSM4(r, pBh + cB);
                bh[0][0] = r[0]; bh[1][0] = r[1];
                bh[0][1] = r[2]; bh[1][1] = r[3];
                LDSM4(r, pBl + cB);
                bl[0][0] = r[0]; bl[1][0] = r[1];
                bl[0][1] = r[2]; bl[1][1] = r[3];
            }
            #pragma unroll
            for (int mt = 0; mt < 4; mt++)
                #pragma unroll
                for (int nt = 0; nt < 2; nt++) {
                    mma_bf16(acc[mt][nt], ah[mt], bh[nt]);
                    mma_bf16(acc[mt][nt], ah[mt], bl[nt]);
                    mma_bf16(acc[mt][nt], al[mt], bh[nt]);
                }
        }
    }

    const int er = lane >> 2, ec = (lane & 3) * 2;
    #pragma unroll
    for (int nt = 0; nt < 2; nt++) {
        const int col = n0 + warpN * 16 + nt * 8 + ec;
        const float2 bv = *(const float2*)&bias[col];
        #pragma unroll
        for (int mt = 0; mt < 4; mt++) {
            const int r0 = m0 + warpM * 64 + mt * 16 + er;
            float t00 = tanhf(acc[mt][nt][0] + bv.x);
            float t01 = tanhf(acc[mt][nt][1] + bv.y);
            float t10 = tanhf(acc[mt][nt][2] + bv.x);
            float t11 = tanhf(acc[mt][nt][3] + bv.y);
            *(float2*)&T[(size_t)r0 * N + col]       = make_float2(t00, t01);
            *(float2*)&T[(size_t)(r0 + 8) * N + col] = make_float2(t10, t11);
        }
    }
}

// ---------------- layer2 split-K partial GEMM (M=1024, N=64, K=2048) ----------------
__global__ void gemm_l2_partial(const float* __restrict__ A, const float* __restrict__ Bw,
                                float* __restrict__ part) {
    const int BM = 64, BN = 64, BK = 16, TM = 4, TN = 4;
    __shared__ float As[BK][BM];
    __shared__ float Bs[BK][BN];
    const int tid  = threadIdx.x;
    const int tcol = tid % (BN / TN);
    const int trow = tid / (BN / TN);
    const int kp = blockIdx.x;
    const int m0 = blockIdx.y * BM;
    const int kbeg = kp * 256, kend = kbeg + 256;
    const int kmax_thr = (tcol * 4 + 4) * 32;

    float acc[TM][TN];
    #pragma unroll
    for (int i = 0; i < TM; i++)
        #pragma unroll
        for (int j = 0; j < TN; j++) acc[i][j] = 0.f;

    for (int k0 = kbeg; k0 < kend; k0 += BK) {
        #pragma unroll
        for (int idx = tid; idx < BM * BK; idx += 256) {
            int m = idx / BK, kk = idx % BK;
            As[kk][m] = A[(size_t)(m0 + m) * DH + k0 + kk];
        }
        #pragma unroll
        for (int idx = tid; idx < BN * BK; idx += 256) {
            int n = idx / BK, kk = idx % BK;
            Bs[kk][n] = Bw[(size_t)n * DH + k0 + kk];
        }
        __syncthreads();
        if (k0 < kmax_thr) {
            #pragma unroll
            for (int kk = 0; kk < BK; kk++) {
                float ar[TM], br[TN];
                #pragma unroll
                for (int i = 0; i < TM; i++) ar[i] = As[kk][trow * TM + i];
                #pragma unroll
                for (int j = 0; j < TN; j++) br[j] = Bs[kk][tcol * TN + j];
                #pragma unroll
                for (int i = 0; i < TM; i++)
                    #pragma unroll
                    for (int j = 0; j < TN; j++)
                        acc[i][j] = fmaf(ar[i], br[j], acc[i][j]);
            }
        }
        __syncthreads();
    }
    #pragma unroll
    for (int i = 0; i < TM; i++) {
        int m = m0 + trow * TM + i;
        #pragma unroll
        for (int j = 0; j < TN; j++) {
            int n = tcol * TN + j;
            part[(size_t)kp * BATCH * DIMN + (size_t)m * DIMN + n] = acc[i][j];
        }
    }
}

// ---------------- Jacobian chain (linear domain, d recomputed from t) ----------------
// Block per (dim i, batch-group of 8); w1d/v0c/w2c staged in SMEM, shared by 8 warps.
__global__ void __launch_bounds__(256)
grad_kernel(const float* __restrict__ w1d, const float* __restrict__ v0c,
            const float* __restrict__ w2c,
            const __nv_bfloat16* __restrict__ t1h, const __nv_bfloat16* __restrict__ t1l,
            const float* __restrict__ t2,
            const float* __restrict__ gate, int use_gate,
            float* __restrict__ ldjc) {
    __shared__ float s_w1[HID][HID + 1];
    __shared__ float s_v0[HID];
    __shared__ float s_w2[HID];
    const int i = blockIdx.x;
    const int tid = threadIdx.x;
    for (int idx = tid; idx < HID * HID; idx += 256) {
        int r = idx >> 5, c = idx & 31;
        s_w1[r][c] = w1d[i * 1024 + r * 32 + c];
    }
    if (tid < HID) {
        s_v0[tid] = v0c[i * 32 + tid];
        s_w2[tid] = w2c[i * 32 + tid];
    }
    __syncthreads();
    const int warp = tid >> 5, lane = tid & 31;
    const int b = blockIdx.y * 8 + warp;
    const size_t off = (size_t)b * DH + i * HID + lane;

    float t1v = __bfloat162float(t1h[off]) + __bfloat162float(t1l[off]);
    float u1 = s_v0[lane] * (1.f - t1v * t1v);
    float acc = 0.f;
    #pragma unroll
    for (int k = 0; k < HID; k++) {
        float uk = __shfl_sync(0xffffffffu, u1, k);
        acc = fmaf(s_w1[lane][k], uk, acc);
    }
    float t2v = t2[off];
    float term = s_w2[lane] * acc * (1.f - t2v * t2v);
    #pragma unroll
    for (int o = 16; o; o >>= 1) term += __shfl_down_sync(0xffffffffu, term, o);
    if (lane == 0) {
        float c;
        if (use_gate) {
            float g = gate[0];
            c = log1pf(term * expf(g)) - log1pf(expf(g));
        } else {
            c = logf(term);
        }
        ldjc[(size_t)b * DIMN + i] = c;
    }
}

// ---------------- fused split-K reduce + gate mix + reversal + ldj / final ----------
__global__ void __launch_bounds__(256)
mix_kernel(const float* __restrict__ part, const float* __restrict__ b2,
           const float* __restrict__ ldjc, const float* __restrict__ gate,
           int flow, const float* __restrict__ xin, float* __restrict__ xout,
           float* __restrict__ ldj, float* __restrict__ outf) {
    const int warp = threadIdx.x >> 5, lane = threadIdx.x & 31;
    const int b = blockIdx.x * 8 + warp;

    float sum = ldjc[(size_t)b * DIMN + lane] + ldjc[(size_t)b * DIMN + 32 + lane];

    float h0 = b2[lane], h1 = b2[lane + 32];
    #pragma unroll
    for (int kp = 0; kp < 8; kp++) {
        h0 += part[(size_t)kp * BATCH * DIMN + b * 64 + lane];
        h1 += part[(size_t)kp * BATCH * DIMN + b * 64 + 32 + lane];
    }

    if (flow < 2) {
        float gv = gate[0];
        float s = 1.f / (1.f + expf(-gv));
        float o0 = s * h0 + (1.f - s) * xin[b * 64 + lane];
        float o1 = s * h1 + (1.f - s) * xin[b * 64 + 32 + lane];
        xout[b * 64 + 63 - lane] = o0;   // reversal
        xout[b * 64 + 31 - lane] = o1;
        #pragma unroll
        for (int o = 16; o; o >>= 1) sum += __shfl_down_sync(0xffffffffu, sum, o);
        if (lane == 0) {
            if (flow == 0) ldj[b] = sum;
            else           ldj[b] += sum;
        }
    } else {
        sum += -0.5f * (h0 * h0 + h1 * h1) - LOG2PI_F;
        #pragma unroll
        for (int o = 16; o; o >>= 1) sum += __shfl_down_sync(0xffffffffu, sum, o);
        if (lane == 0) outf[b] = ldj[b] + sum;
    }
}

// ---------------- launch ----------------
extern "C" void kernel_launch(void* const* d_in, const int* in_sizes, int n_in,
                              void* d_out, int out_size) {
    const float* x = (const float*)d_in[0];
    const float* gates[2] = { (const float*)d_in[28], (const float*)d_in[29] };

    float *wn0, *wn2, *t2, *xa, *xb, *ldj, *ldjc, *part, *w1d, *v0c, *w2c;
    __nv_bfloat16 *w1h, *w1l, *t1h, *t1l;
    cudaGetSymbolAddress((void**)&wn0,  g_wn0);
    cudaGetSymbolAddress((void**)&wn2,  g_wn2);
    cudaGetSymbolAddress((void**)&w1h,  g_w1h);
    cudaGetSymbolAddress((void**)&w1l,  g_w1l);
    cudaGetSymbolAddress((void**)&w1d,  g_w1d);
    cudaGetSymbolAddress((void**)&v0c,  g_v0c);
    cudaGetSymbolAddress((void**)&w2c,  g_w2c);
    cudaGetSymbolAddress((void**)&t1h,  g_t1h);
    cudaGetSymbolAddress((void**)&t1l,  g_t1l);
    cudaGetSymbolAddress((void**)&t2,   g_t2);
    cudaGetSymbolAddress((void**)&xa,   g_xa);
    cudaGetSymbolAddress((void**)&xb,   g_xb);
    cudaGetSymbolAddress((void**)&ldj,  g_ldj);
    cudaGetSymbolAddress((void**)&ldjc, g_ldjc);
    cudaGetSymbolAddress((void**)&part, g_part);

    const size_t SZ1 = (size_t)DH * DH;

    const int DYN_SMEM = 3 * 24576;
    cudaFuncSetAttribute(gemm_mma_l1, cudaFuncAttributeMaxDynamicSharedMemorySize, DYN_SMEM);

    PtrSet p0, p1, p2;
    for (int f = 0; f < 3; f++) {
        p0.W[f]  = (const float*)d_in[1 + f * 9 + 0];
        p0.dw[f] = (const float*)d_in[1 + f * 9 + 1];
        p1.W[f]  = (const float*)d_in[1 + f * 9 + 3];
        p1.dw[f] = (const float*)d_in[1 + f * 9 + 4];
        p2.W[f]  = (const float*)d_in[1 + f * 9 + 6];
        p2.dw[f] = (const float*)d_in[1 + f * 9 + 7];
    }
    prep0_fused<<<dim3(256, 3),  256>>>(p0, wn0, v0c);
    prep1_fused<<<dim3(DH, 3),   256, DH * sizeof(float)>>>(p1, w1h, w1l, w1d);
    prep2_fused<<<dim3(DIMN, 3), 256, DH * sizeof(float)>>>(p2, wn2, w2c);

    const float* xcur = x;
    for (int f = 0; f < 3; f++) {
        const float* b0 = (const float*)d_in[1 + f * 9 + 2];
        const float* b1 = (const float*)d_in[1 + f * 9 + 5];
        const float* b2 = (const float*)d_in[1 + f * 9 + 8];

        gemm_l0<<<dim3(32, 16), 256>>>(xcur, wn0 + (size_t)f * DH * DIMN, b0, t1h, t1l);
        gemm_mma_l1<<<256, 256, DYN_SMEM>>>(
            t1h, t1l, w1h + f * SZ1, w1l + f * SZ1, b1, t2);
        gemm_l2_partial<<<dim3(8, 16), 256>>>(t2, wn2 + (size_t)f * DIMN * DH, part);

        grad_kernel<<<dim3(DIMN, BATCH / 8), 256>>>(
            w1d + f * 64 * 1024, v0c + f * 2048, w2c + f * 2048,
            t1h, t1l, t2,
            (f < 2) ? gates[f] : nullptr, (f < 2) ? 1 : 0, ldjc);

        float* xnext = (f == 0) ? xa : xb;
        mix_kernel<<<128, 256>>>(
            part, b2, ldjc, (f < 2) ? gates[f] : nullptr, f,
            xcur, xnext, ldj, (float*)d_out);
        xcur = xnext;
    }
}

// round 12
// speedup vs baseline: 1.0009x; 1.0009x over previous
#include <cuda_runtime.h>
#include <cuda_bf16.h>
#include <math.h>
#include <stdint.h>

#define DIMN 64
#define HID 32
#define BATCH 1024
#define DH 2048   // DIMN*HID
#define LOG2PI_F 1.8378770664093453f

// ---------------- scratch (device globals; no allocation allowed) ----------------
// g_w1h/g_w1l rely on static zero-init for the masked region (prep1 writes only j < dhi).
__device__ float g_wn0[3 * (size_t)DH * DIMN];
__device__ float g_wn2[3 * (size_t)DIMN * DH];
__device__ __nv_bfloat16 g_w1h[3 * (size_t)DH * DH];
__device__ __nv_bfloat16 g_w1l[3 * (size_t)DH * DH];
__device__ float g_w1d[3 * 64 * 32 * 32];   // compact f32 diag blocks of wn1
__device__ float g_v0c[3 * 64 * 32];        // compact diag column of wn0
__device__ float g_w2c[3 * 64 * 32];        // compact diag row of wn2
__device__ __nv_bfloat16 g_t1h[(size_t)BATCH * DH];
__device__ __nv_bfloat16 g_t1l[(size_t)BATCH * DH];
__device__ float g_t2[BATCH*DH];
__device__ float g_part[8 * BATCH * DIMN];
__device__ float g_ldjc[BATCH * DIMN];
__device__ float g_xa[BATCH*DIMN];
__device__ float g_xb[BATCH*DIMN];
__device__ float g_ldj[BATCH];

struct PtrSet { const float* W[3]; const float* dw[3]; };

// ---------------- helpers ----------------
__device__ __forceinline__ uint32_t smem_u32(const void* p) {
    uint32_t a;
    asm("{ .reg .u64 t; cvta.to.shared.u64 t, %1; cvt.u32.u64 %0, t; }" : "=r"(a) : "l"(p));
    return a;
}
__device__ __forceinline__ void cp_async16(uint32_t dst, const void* src) {
    asm volatile("cp.async.cg.shared.global [%0], [%1], 16;" :: "r"(dst), "l"(src) : "memory");
}
__device__ __forceinline__ void cp_commit() {
    asm volatile("cp.async.commit_group;" ::: "memory");
}
#define CP_WAIT(n) asm volatile("cp.async.wait_group %0;" :: "n"(n) : "memory")

#define LDSM4(r, a) \
    asm volatile("ldmatrix.sync.aligned.m8n8.x4.shared.b16 {%0,%1,%2,%3}, [%4];" \
        : "=r"((r)[0]), "=r"((r)[1]), "=r"((r)[2]), "=r"((r)[3]) : "r"(a))

__device__ __forceinline__ void mma_bf16(float* c, const uint32_t* a, const uint32_t* b) {
    asm volatile("mma.sync.aligned.m16n8k16.row.col.f32.bf16.bf16.f32 "
                 "{%0,%1,%2,%3}, {%4,%5,%6,%7}, {%8,%9}, {%0,%1,%2,%3};"
                 : "+f"(c[0]), "+f"(c[1]), "+f"(c[2]), "+f"(c[3])
                 : "r"(a[0]), "r"(a[1]), "r"(a[2]), "r"(a[3]), "r"(b[0]), "r"(b[1]));
}
__device__ __forceinline__ void split_bf16(float v, __nv_bfloat16& h, __nv_bfloat16& l) {
    h = __float2bfloat16(v);
    l = __float2bfloat16(v - __bfloat162float(h));
}

// ---------------- prep0 (W0: 2048x64), warp-per-row, fused over 3 flows ---------------
__global__ void __launch_bounds__(256)
prep0_fused(PtrSet ps, float* __restrict__ wn0_base, float* __restrict__ v0c_base) {
    const int f = blockIdx.y;
    const int o = blockIdx.x * 8 + (threadIdx.x >> 5);   // row 0..2047
    const int lane = threadIdx.x & 31;
    const int bi = o >> 5;                               // diag col index (ib=1)
    const float* Wr = ps.W[f] + (size_t)o * DIMN;
    float* wn = wn0_base + (size_t)f * DH * DIMN + (size_t)o * DIMN;

    const int j0 = lane, j1 = lane + 32;
    float v0 = Wr[j0], v1 = Wr[j1];
    float w0 = (j0 > bi) ? 0.f : ((j0 == bi) ? expf(v0) : v0);
    float w1 = (j1 > bi) ? 0.f : ((j1 == bi) ? expf(v1) : v1);
    float ss = w0 * w0 + w1 * w1;
    #pragma unroll
    for (int off = 16; off; off >>= 1) ss += __shfl_xor_sync(0xffffffffu, ss, off);
    const float scale = expf(ps.dw[f][o]) / sqrtf(ss);
    wn[j0] = w0 * scale;
    wn[j1] = w1 * scale;
    if (j0 == bi) v0c_base[f * 2048 + o] = w0 * scale;
    if (j1 == bi) v0c_base[f * 2048 + o] = w1 * scale;
}

// ---------------- prep1 (W1: 2048x2048) -> bf16 hi/lo + f32 diag, fused --------------
__global__ void prep1_fused(PtrSet ps,
                            __nv_bfloat16* __restrict__ wh_base,
                            __nv_bfloat16* __restrict__ wl_base,
                            float* __restrict__ diag_base) {
    extern __shared__ float sw[];
    __shared__ float red[8];
    const int f = blockIdx.y;
    const int o = blockIdx.x;            // 0..2047
    const int bi = o >> 5, r = o & 31;
    const int dlo = bi * 32, dhi = dlo + 32;
    const float* Wr = ps.W[f] + (size_t)o * DH;
    __nv_bfloat16* wh = wh_base + (size_t)f * DH * DH + (size_t)o * DH;
    __nv_bfloat16* wl = wl_base + (size_t)f * DH * DH + (size_t)o * DH;
    float* diag = diag_base + f * 64 * 1024;

    float ss = 0.f;
    for (int j = threadIdx.x; j < dhi; j += blockDim.x) {
        float Wv = Wr[j];
        float w = (j >= dlo) ? expf(Wv) : Wv;
        sw[j] = w;
        ss += w * w;
    }
    #pragma unroll
    for (int off = 16; off; off >>= 1) ss += __shfl_down_sync(0xffffffffu, ss, off);
    if ((threadIdx.x & 31) == 0) red[threadIdx.x >> 5] = ss;
    __syncthreads();
    if (threadIdx.x == 0) {
        float v = 0.f;
        for (int w = 0; w < 8; w++) v += red[w];
        red[0] = v;
    }
    __syncthreads();
    const float scale = expf(ps.dw[f][o]) / sqrtf(red[0]);
    for (int j = threadIdx.x; j < dhi; j += blockDim.x) {
        float v = sw[j] * scale;
        __nv_bfloat16 h, l;
        split_bf16(v, h, l);
        wh[j] = h;
        wl[j] = l;
    }
    if (threadIdx.x < 32)
        diag[bi * 1024 + r * 32 + threadIdx.x] = sw[dlo + threadIdx.x] * scale;
}

// ---------------- prep2 (W2: 64x2048) -> f32 + compact diag, fused ----------------
__global__ void prep2_fused(PtrSet ps, float* __restrict__ wn2_base,
                            float* __restrict__ w2c_base) {
    extern __shared__ float sw[];
    __shared__ float red[8];
    const int f = blockIdx.y;
    const int o = blockIdx.x;            // 0..63
    const int dlo = o * 32, dhi = dlo + 32;
    const float* Wr = ps.W[f] + (size_t)o * DH;
    float* wn = wn2_base + (size_t)f * DIMN * DH + (size_t)o * DH;

    float ss = 0.f;
    for (int j = threadIdx.x; j < DH; j += blockDim.x) {
        float Wv = Wr[j];
        float w = (j >= dhi) ? 0.f : ((j >= dlo) ? expf(Wv) : Wv);
        sw[j] = w;
        ss += w * w;
    }
    #pragma unroll
    for (int off = 16; off; off >>= 1) ss += __shfl_down_sync(0xffffffffu, ss, off);
    if ((threadIdx.x & 31) == 0) red[threadIdx.x >> 5] = ss;
    __syncthreads();
    if (threadIdx.x == 0) {
        float v = 0.f;
        for (int w = 0; w < 8; w++) v += red[w];
        red[0] = v;
    }
    __syncthreads();
    const float scale = expf(ps.dw[f][o]) / sqrtf(red[0]);
    for (int j = threadIdx.x; j < DH; j += blockDim.x) wn[j] = sw[j] * scale;
    if (threadIdx.x < 32)
        w2c_base[f * 2048 + o * 32 + threadIdx.x] = sw[dlo + threadIdx.x] * scale;
}

// ---------------- layer0 GEMM: t1 = tanh(x @ wn0^T + b0), bf16 hi/lo out ------------
__global__ void __launch_bounds__(256)
gemm_l0(const float* __restrict__ A, const float* __restrict__ Bw,
        const float* __restrict__ bias,
        __nv_bfloat16* __restrict__ Th, __nv_bfloat16* __restrict__ Tl) {
    __shared__ float As[16][68];
    __shared__ float Bs[16][68];
    const int tid  = threadIdx.x;
    const int tcol = tid & 15;
    const int trow = tid >> 4;
    const int m0 = blockIdx.y * 64;
    const int nx = 31 - (int)blockIdx.x;    // longest-first
    const int n0 = nx * 64;
    const int keff = 2 * nx + 2;
    const int nk = (keff + 15) >> 4;        // 1..4

    const int rL = tid >> 2;                // 0..63
    const int kL = (tid & 3) * 4;
    const float* pA = A  + (size_t)(m0 + rL) * DIMN + kL;
    const float* pB = Bw + (size_t)(n0 + rL) * DIMN + kL;

    float acc[4][4];
    #pragma unroll
    for (int i = 0; i < 4; i++)
        #pragma unroll
        for (int j = 0; j < 4; j++) acc[i][j] = 0.f;

    for (int t = 0; t < nk; t++) {
        float4 av = *(const float4*)(pA + t * 16);
        float4 bv = *(const float4*)(pB + t * 16);
        As[kL+0][rL] = av.x; As[kL+1][rL] = av.y; As[kL+2][rL] = av.z; As[kL+3][rL] = av.w;
        Bs[kL+0][rL] = bv.x; Bs[kL+1][rL] = bv.y; Bs[kL+2][rL] = bv.z; Bs[kL+3][rL] = bv.w;
        __syncthreads();
        #pragma unroll
        for (int kk = 0; kk < 16; kk++) {
            float4 a = *(const float4*)&As[kk][trow * 4];
            float4 b = *(const float4*)&Bs[kk][tcol * 4];
            acc[0][0] = fmaf(a.x, b.x, acc[0][0]); acc[0][1] = fmaf(a.x, b.y, acc[0][1]);
            acc[0][2] = fmaf(a.x, b.z, acc[0][2]); acc[0][3] = fmaf(a.x, b.w, acc[0][3]);
            acc[1][0] = fmaf(a.y, b.x, acc[1][0]); acc[1][1] = fmaf(a.y, b.y, acc[1][1]);
            acc[1][2] = fmaf(a.y, b.z, acc[1][2]); acc[1][3] = fmaf(a.y, b.w, acc[1][3]);
            acc[2][0] = fmaf(a.z, b.x, acc[2][0]); acc[2][1] = fmaf(a.z, b.y, acc[2][1]);
            acc[2][2] = fmaf(a.z, b.z, acc[2][2]); acc[2][3] = fmaf(a.z, b.w, acc[2][3]);
            acc[3][0] = fmaf(a.w, b.x, acc[3][0]); acc[3][1] = fmaf(a.w, b.y, acc[3][1]);
            acc[3][2] = fmaf(a.w, b.z, acc[3][2]); acc[3][3] = fmaf(a.w, b.w, acc[3][3]);
        }
        __syncthreads();
    }

    const int ncol = n0 + tcol * 4;
    const float4 bv = *(const float4*)&bias[ncol];
    const float bcol[4] = { bv.x, bv.y, bv.z, bv.w };
    #pragma unroll
    for (int i = 0; i < 4; i++) {
        const int m = m0 + trow * 4 + i;
        __nv_bfloat16 hv[4], lv[4];
        #pragma unroll
        for (int c = 0; c < 4; c++) {
            float tv = tanhf(acc[i][c] + bcol[c]);
            split_bf16(tv, hv[c], lv[c]);
        }
        *(uint2*)&Th[(size_t)m * DH + ncol] = *(uint2*)hv;
        *(uint2*)&Tl[(size_t)m * DH + ncol] = *(uint2*)lv;
    }
}

// ---------------- layer1 HMMA GEMM (split-bf16, block-triangular K-early-exit) ----------
__global__ void __launch_bounds__(256, 2)
gemm_mma_l1(const __nv_bfloat16* __restrict__ Ah, const __nv_bfloat16* __restrict__ Al,
            const __nv_bfloat16* __restrict__ Bh, const __nv_bfloat16* __restrict__ Bl,
            const float* __restrict__ bias, float* __restrict__ T) {
    extern __shared__ char smem[];
    const int K = DH, N = DH;
    const int tid = threadIdx.x, lane = tid & 31, wid = tid >> 5;
    const int warpM = wid & 1, warpN = wid >> 1;   // 2 x 4 warps, warp tile 64x16
    const int bid = blockIdx.x;
    const int jn = 31 - (bid >> 3);
    const int mi = bid & 7;
    const int m0 = mi * 128, n0 = jn * 64;
    const int NK = min(64, 2 * jn + 4);
    const uint32_t sbase = smem_u32(smem);

    const __nv_bfloat16* gA[2] = { Ah + (size_t)m0 * K, Al + (size_t)m0 * K };
    const __nv_bfloat16* gB[2] = { Bh + (size_t)n0 * K, Bl + (size_t)n0 * K };

    float acc[4][2][4];
    #pragma unroll
    for (int i = 0; i < 4; i++)
        #pragma unroll
        for (int j = 0; j < 2; j++)
            #pragma unroll
            for (int e = 0; e < 4; e++) acc[i][j][e] = 0.f;

    const int pr_row = tid >> 2;
    const int pr_ch  = tid & 3;
    #define PREFETCH(t) do {                                                          \
        uint32_t stb = sbase + ((t) % 3) * 24576;                                     \
        _Pragma("unroll")                                                             \
        for (int a = 0; a < 2; a++) {                                                 \
            _Pragma("unroll")                                                         \
            for (int j = 0; j < 2; j++) {                                             \
                int row = pr_row + j * 64;                                            \
                const __nv_bfloat16* src = gA[a] + (size_t)row * K + (t) * 32 + pr_ch * 8; \
                uint32_t dst = stb + a * 8192 + row * 64 + ((pr_ch ^ ((row >> 1) & 3)) * 16); \
                cp_async16(dst, src);                                                 \
            }                                                                         \
            const __nv_bfloat16* srcb = gB[a] + (size_t)pr_row * K + (t) * 32 + pr_ch * 8; \
            uint32_t dstb = stb + 16384 + a * 4096 + pr_row * 64                      \
                          + ((pr_ch ^ ((pr_row >> 1) & 3)) * 16);                     \
            cp_async16(dstb, srcb);                                                   \
        }                                                                             \
        cp_commit();                                                                  \
    } while (0)

    PREFETCH(0);
    PREFETCH(1);

    const int rlA = warpM * 64 + (lane & 15);
    const int rlB = warpN * 16 + (lane & 15);
    const int hi  = lane >> 4;
    const int xA  = (rlA >> 1) & 3;
    const int xB  = (rlB >> 1) & 3;

    for (int t = 0; t < NK; t++) {
        if (t + 1 < NK) { CP_WAIT(1); } else { CP_WAIT(0); }
        __syncthreads();
        if (t + 2 < NK) PREFETCH(t + 2);

        const uint32_t stb = sbase + (t % 3) * 24576;
        const uint32_t pAh = stb + rlA * 64;
        const uint32_t pAl = pAh + 8192;
        const uint32_t pBh = stb + 16384 + rlB * 64;
        const uint32_t pBl = pBh + 4096;

        #pragma unroll
        for (int ks = 0; ks < 2; ks++) {
            const uint32_t cA = (uint32_t)(((ks * 2 + hi) ^ xA) * 16);
            const uint32_t cB = (uint32_t)(((ks * 2 + hi) ^ xB) * 16);
            uint32_t ah[4][4], al[4][4], bh[2][2], bl[2][2];
            #pragma unroll
            for (int mt = 0; mt < 4; mt++) {
                LDSM4(ah[mt], pAh + mt * 1024 + cA);
                LDSM4(al[mt], pAl + mt * 1024 + cA);
            }
            {
                uint32_t r[4];
                LDSM4(r, pBh + cB);
                bh[0][0] = r[0]; bh[1][0] = r[1];
                bh[0][1] = r[2]; bh[1][1] = r[3];
                LDSM4(r, pBl + cB);
                bl[0][0] = r[0]; bl[1][0] = r[1];
                bl[0][1] = r[2]; bl[1][1] = r[3];
            }
            #pragma unroll
            for (int mt = 0; mt < 4; mt++)
                #pragma unroll
                for (int nt = 0; nt < 2; nt++) {
                    mma_bf16(acc[mt][nt], ah[mt], bh[nt]);
                    mma_bf16(acc[mt][nt], ah[mt], bl[nt]);
                    mma_bf16(acc[mt][nt], al[mt], bh[nt]);
                }
        }
    }

    const int er = lane >> 2, ec = (lane & 3) * 2;
    #pragma unroll
    for (int nt = 0; nt < 2; nt++) {
        const int col = n0 + warpN * 16 + nt * 8 + ec;
        const float2 bv = *(const float2*)&bias[col];
        #pragma unroll
        for (int mt = 0; mt < 4; mt++) {
            const int r0 = m0 + warpM * 64 + mt * 16 + er;
            float t00 = tanhf(acc[mt][nt][0] + bv.x);
            float t01 = tanhf(acc[mt][nt][1] + bv.y);
            float t10 = tanhf(acc[mt][nt][2] + bv.x);
            float t11 = tanhf(acc[mt][nt][3] + bv.y);
            *(float2*)&T[(size_t)r0 * N + col]       = make_float2(t00, t01);
            *(float2*)&T[(size_t)(r0 + 8) * N + col] = make_float2(t10, t11);
        }
    }
}

// ---------------- layer2 split-K partial GEMM (M=1024, N=64, K=2048) ----------------
__global__ void gemm_l2_partial(const float* __restrict__ A, const float* __restrict__ Bw,
                                float* __restrict__ part) {
    const int BM = 64, BN = 64, BK = 16, TM = 4, TN = 4;
    __shared__ float As[BK][BM];
    __shared__ float Bs[BK][BN];
    const int tid  = threadIdx.x;
    const int tcol = tid % (BN / TN);
    const int trow = tid / (BN / TN);
    const int kp = blockIdx.x;
    const int m0 = blockIdx.y * BM;
    const int kbeg = kp * 256, kend = kbeg + 256;
    const int kmax_thr = (tcol * 4 + 4) * 32;

    float acc[TM][TN];
    #pragma unroll
    for (int i = 0; i < TM; i++)
        #pragma unroll
        for (int j = 0; j < TN; j++) acc[i][j] = 0.f;

    for (int k0 = kbeg; k0 < kend; k0 += BK) {
        #pragma unroll
        for (int idx = tid; idx < BM * BK; idx += 256) {
            int m = idx / BK, kk = idx % BK;
            As[kk][m] = A[(size_t)(m0 + m) * DH + k0 + kk];
        }
        #pragma unroll
        for (int idx = tid; idx < BN * BK; idx += 256) {
            int n = idx / BK, kk = idx % BK;
            Bs[kk][n] = Bw[(size_t)n * DH + k0 + kk];
        }
        __syncthreads();
        if (k0 < kmax_thr) {
            #pragma unroll
            for (int kk = 0; kk < BK; kk++) {
                float ar[TM], br[TN];
                #pragma unroll
                for (int i = 0; i < TM; i++) ar[i] = As[kk][trow * TM + i];
                #pragma unroll
                for (int j = 0; j < TN; j++) br[j] = Bs[kk][tcol * TN + j];
                #pragma unroll
                for (int i = 0; i < TM; i++)
                    #pragma unroll
                    for (int j = 0; j < TN; j++)
                        acc[i][j] = fmaf(ar[i], br[j], acc[i][j]);
            }
        }
        __syncthreads();
    }
    #pragma unroll
    for (int i = 0; i < TM; i++) {
        int m = m0 + trow * TM + i;
        #pragma unroll
        for (int j = 0; j < TN; j++) {
            int n = tcol * TN + j;
            part[(size_t)kp * BATCH * DIMN + (size_t)m * DIMN + n] = acc[i][j];
        }
    }
}

// ---------------- Jacobian chain (linear domain, d recomputed from t) ----------------
// Block per (dim i, batch-group of 8); w1d/v0c/w2c staged in SMEM, shared by 8 warps.
__global__ void __launch_bounds__(256)
grad_kernel(const float* __restrict__ w1d, const float* __restrict__ v0c,
            const float* __restrict__ w2c,
            const __nv_bfloat16* __restrict__ t1h, const __nv_bfloat16* __restrict__ t1l,
            const float* __restrict__ t2,
            const float* __restrict__ gate, int use_gate,
            float* __restrict__ ldjc) {
    __shared__ float s_w1[HID][HID + 1];
    __shared__ float s_v0[HID];
    __shared__ float s_w2[HID];
    const int i = blockIdx.x;
    const int tid = threadIdx.x;
    for (int idx = tid; idx < HID * HID; idx += 256) {
        int r = idx >> 5, c = idx & 31;
        s_w1[r][c] = w1d[i * 1024 + r * 32 + c];
    }
    if (tid < HID) {
        s_v0[tid] = v0c[i * 32 + tid];
        s_w2[tid] = w2c[i * 32 + tid];
    }
    __syncthreads();
    const int warp = tid >> 5, lane = tid & 31;
    const int b = blockIdx.y * 8 + warp;
    const size_t off = (size_t)b * DH + i * HID + lane;

    float t1v = __bfloat162float(t1h[off]) + __bfloat162float(t1l[off]);
    float u1 = s_v0[lane] * (1.f - t1v * t1v);
    float acc = 0.f;
    #pragma unroll
    for (int k = 0; k < HID; k++) {
        float uk = __shfl_sync(0xffffffffu, u1, k);
        acc = fmaf(s_w1[lane][k], uk, acc);
    }
    float t2v = t2[off];
    float term = s_w2[lane] * acc * (1.f - t2v * t2v);
    #pragma unroll
    for (int o = 16; o; o >>= 1) term += __shfl_down_sync(0xffffffffu, term, o);
    if (lane == 0) {
        float c;
        if (use_gate) {
            float g = gate[0];
            c = log1pf(term * expf(g)) - log1pf(expf(g));
        } else {
            c = logf(term);
        }
        ldjc[(size_t)b * DIMN + i] = c;
    }
}

// ---------------- fused split-K reduce + gate mix + reversal + ldj / final ----------
__global__ void __launch_bounds__(256)
mix_kernel(const float* __restrict__ part, const float* __restrict__ b2,
           const float* __restrict__ ldjc, const float* __restrict__ gate,
           int flow, const float* __restrict__ xin, float* __restrict__ xout,
           float* __restrict__ ldj, float* __restrict__ outf) {
    const int warp = threadIdx.x >> 5, lane = threadIdx.x & 31;
    const int b = blockIdx.x * 8 + warp;

    float sum = ldjc[(size_t)b * DIMN + lane] + ldjc[(size_t)b * DIMN + 32 + lane];

    float h0 = b2[lane], h1 = b2[lane + 32];
    #pragma unroll
    for (int kp = 0; kp < 8; kp++) {
        h0 += part[(size_t)kp * BATCH * DIMN + b * 64 + lane];
        h1 += part[(size_t)kp * BATCH * DIMN + b * 64 + 32 + lane];
    }

    if (flow < 2) {
        float gv = gate[0];
        float s = 1.f / (1.f + expf(-gv));
        float o0 = s * h0 + (1.f - s) * xin[b * 64 + lane];
        float o1 = s * h1 + (1.f - s) * xin[b * 64 + 32 + lane];
        xout[b * 64 + 63 - lane] = o0;   // reversal
        xout[b * 64 + 31 - lane] = o1;
        #pragma unroll
        for (int o = 16; o; o >>= 1) sum += __shfl_down_sync(0xffffffffu, sum, o);
        if (lane == 0) {
            if (flow == 0) ldj[b] = sum;
            else           ldj[b] += sum;
        }
    } else {
        sum += -0.5f * (h0 * h0 + h1 * h1) - LOG2PI_F;
        #pragma unroll
        for (int o = 16; o; o >>= 1) sum += __shfl_down_sync(0xffffffffu, sum, o);
        if (lane == 0) outf[b] = ldj[b] + sum;
    }
}

// ---------------- launch ----------------
extern "C" void kernel_launch(void* const* d_in, const int* in_sizes, int n_in,
                              void* d_out, int out_size) {
    const float* x = (const float*)d_in[0];
    const float* gates[2] = { (const float*)d_in[28], (const float*)d_in[29] };

    float *wn0, *wn2, *t2, *xa, *xb, *ldj, *ldjc, *part, *w1d, *v0c, *w2c;
    __nv_bfloat16 *w1h, *w1l, *t1h, *t1l;
    cudaGetSymbolAddress((void**)&wn0,  g_wn0);
    cudaGetSymbolAddress((void**)&wn2,  g_wn2);
    cudaGetSymbolAddress((void**)&w1h,  g_w1h);
    cudaGetSymbolAddress((void**)&w1l,  g_w1l);
    cudaGetSymbolAddress((void**)&w1d,  g_w1d);
    cudaGetSymbolAddress((void**)&v0c,  g_v0c);
    cudaGetSymbolAddress((void**)&w2c,  g_w2c);
    cudaGetSymbolAddress((void**)&t1h,  g_t1h);
    cudaGetSymbolAddress((void**)&t1l,  g_t1l);
    cudaGetSymbolAddress((void**)&t2,   g_t2);
    cudaGetSymbolAddress((void**)&xa,   g_xa);
    cudaGetSymbolAddress((void**)&xb,   g_xb);
    cudaGetSymbolAddress((void**)&ldj,  g_ldj);
    cudaGetSymbolAddress((void**)&ldjc, g_ldjc);
    cudaGetSymbolAddress((void**)&part, g_part);

    const size_t SZ1 = (size_t)DH * DH;

    const int DYN_SMEM = 3 * 24576;
    cudaFuncSetAttribute(gemm_mma_l1, cudaFuncAttributeMaxDynamicSharedMemorySize, DYN_SMEM);

    PtrSet p0, p1, p2;
    for (int f = 0; f < 3; f++) {
        p0.W[f]  = (const float*)d_in[1 + f * 9 + 0];
        p0.dw[f] = (const float*)d_in[1 + f * 9 + 1];
        p1.W[f]  = (const float*)d_in[1 + f * 9 + 3];
        p1.dw[f] = (const float*)d_in[1 + f * 9 + 4];
        p2.W[f]  = (const float*)d_in[1 + f * 9 + 6];
        p2.dw[f] = (const float*)d_in[1 + f * 9 + 7];
    }
    prep0_fused<<<dim3(256, 3),  256>>>(p0, wn0, v0c);
    prep1_fused<<<dim3(DH, 3),   256, DH * sizeof(float)>>>(p1, w1h, w1l, w1d);
    prep2_fused<<<dim3(DIMN, 3), 256, DH * sizeof(float)>>>(p2, wn2, w2c);

    const float* xcur = x;
    for (int f = 0; f < 3; f++) {
        const float* b0 = (const float*)d_in[1 + f * 9 + 2];
        const float* b1 = (const float*)d_in[1 + f * 9 + 5];
        const float* b2 = (const float*)d_in[1 + f * 9 + 8];

        gemm_l0<<<dim3(32, 16), 256>>>(xcur, wn0 + (size_t)f * DH * DIMN, b0, t1h, t1l);
        gemm_mma_l1<<<256, 256, DYN_SMEM>>>(
            t1h, t1l, w1h + f * SZ1, w1l + f * SZ1, b1, t2);
        gemm_l2_partial<<<dim3(8, 16), 256>>>(t2, wn2 + (size_t)f * DIMN * DH, part);

        grad_kernel<<<dim3(DIMN, BATCH / 8), 256>>>(
            w1d + f * 64 * 1024, v0c + f * 2048, w2c + f * 2048,
            t1h, t1l, t2,
            (f < 2) ? gates[f] : nullptr, (f < 2) ? 1 : 0, ldjc);

        float* xnext = (f == 0) ? xa : xb;
        mix_kernel<<<128, 256>>>(
            part, b2, ldjc, (f < 2) ? gates[f] : nullptr, f,
            xcur, xnext, ldj, (float*)d_out);
        xcur = xnext;
    }
}

// round 13
// speedup vs baseline: 1.0082x; 1.0073x over previous
#include <cuda_runtime.h>
#include <cuda_bf16.h>
#include <math.h>
#include <stdint.h>

#define DIMN 64
#define HID 32
#define BATCH 1024
#define DH 2048   // DIMN*HID
#define LOG2PI_F 1.8378770664093453f

// ---------------- scratch (device globals; no allocation allowed) ----------------
// g_w1h/g_w1l rely on static zero-init for the masked region (prep1 writes only j < dhi).
__device__ float g_wn0[3 * (size_t)DH * DIMN];
__device__ float g_wn2[3 * (size_t)DIMN * DH];
__device__ __nv_bfloat16 g_w1h[3 * (size_t)DH * DH];
__device__ __nv_bfloat16 g_w1l[3 * (size_t)DH * DH];
__device__ float g_w1d[3 * 64 * 32 * 32];   // compact f32 diag blocks of wn1
__device__ float g_v0c[3 * 64 * 32];        // compact diag column of wn0
__device__ float g_w2c[3 * 64 * 32];        // compact diag row of wn2
__device__ __nv_bfloat16 g_t1h[(size_t)BATCH * DH];
__device__ __nv_bfloat16 g_t1l[(size_t)BATCH * DH];
__device__ float g_t2[BATCH*DH];
__device__ float g_part[8 * BATCH * DIMN];
__device__ float g_ldjc[BATCH * DIMN];
__device__ float g_xa[BATCH*DIMN];
__device__ float g_xb[BATCH*DIMN];
__device__ float g_ldj[BATCH];

struct PtrSet { const float* W[3]; const float* dw[3]; };

// ---------------- helpers ----------------
__device__ __forceinline__ uint32_t smem_u32(const void* p) {
    uint32_t a;
    asm("{ .reg .u64 t; cvta.to.shared.u64 t, %1; cvt.u32.u64 %0, t; }" : "=r"(a) : "l"(p));
    return a;
}
__device__ __forceinline__ void cp_async16(uint32_t dst, const void* src) {
    asm volatile("cp.async.cg.shared.global [%0], [%1], 16;" :: "r"(dst), "l"(src) : "memory");
}
__device__ __forceinline__ void cp_commit() {
    asm volatile("cp.async.commit_group;" ::: "memory");
}
#define CP_WAIT(n) asm volatile("cp.async.wait_group %0;" :: "n"(n) : "memory")

#define LDSM4(r, a) \
    asm volatile("ldmatrix.sync.aligned.m8n8.x4.shared.b16 {%0,%1,%2,%3}, [%4];" \
        : "=r"((r)[0]), "=r"((r)[1]), "=r"((r)[2]), "=r"((r)[3]) : "r"(a))

__device__ __forceinline__ void mma_bf16(float* c, const uint32_t* a, const uint32_t* b) {
    asm volatile("mma.sync.aligned.m16n8k16.row.col.f32.bf16.bf16.f32 "
                 "{%0,%1,%2,%3}, {%4,%5,%6,%7}, {%8,%9}, {%0,%1,%2,%3};"
                 : "+f"(c[0]), "+f"(c[1]), "+f"(c[2]), "+f"(c[3])
                 : "r"(a[0]), "r"(a[1]), "r"(a[2]), "r"(a[3]), "r"(b[0]), "r"(b[1]));
}
__device__ __forceinline__ void split_bf16(float v, __nv_bfloat16& h, __nv_bfloat16& l) {
    h = __float2bfloat16(v);
    l = __float2bfloat16(v - __bfloat162float(h));
}

// ---------------- prep0 (W0: 2048x64), warp-per-row, fused over 3 flows ---------------
__global__ void __launch_bounds__(256)
prep0_fused(PtrSet ps, float* __restrict__ wn0_base, float* __restrict__ v0c_base) {
    const int f = blockIdx.y;
    const int o = blockIdx.x * 8 + (threadIdx.x >> 5);   // row 0..2047
    const int lane = threadIdx.x & 31;
    const int bi = o >> 5;                               // diag col index (ib=1)
    const float* Wr = ps.W[f] + (size_t)o * DIMN;
    float* wn = wn0_base + (size_t)f * DH * DIMN + (size_t)o * DIMN;

    const int j0 = lane, j1 = lane + 32;
    float v0 = Wr[j0], v1 = Wr[j1];
    float w0 = (j0 > bi) ? 0.f : ((j0 == bi) ? expf(v0) : v0);
    float w1 = (j1 > bi) ? 0.f : ((j1 == bi) ? expf(v1) : v1);
    float ss = w0 * w0 + w1 * w1;
    #pragma unroll
    for (int off = 16; off; off >>= 1) ss += __shfl_xor_sync(0xffffffffu, ss, off);
    const float scale = expf(ps.dw[f][o]) / sqrtf(ss);
    wn[j0] = w0 * scale;
    wn[j1] = w1 * scale;
    if (j0 == bi) v0c_base[f * 2048 + o] = w0 * scale;
    if (j1 == bi) v0c_base[f * 2048 + o] = w1 * scale;
}

// ---------------- prep1 (W1: 2048x2048) -> bf16 hi/lo + f32 diag, fused --------------
__global__ void prep1_fused(PtrSet ps,
                            __nv_bfloat16* __restrict__ wh_base,
                            __nv_bfloat16* __restrict__ wl_base,
                            float* __restrict__ diag_base) {
    extern __shared__ float sw[];
    __shared__ float red[8];
    const int f = blockIdx.y;
    const int o = blockIdx.x;            // 0..2047
    const int bi = o >> 5, r = o & 31;
    const int dlo = bi * 32, dhi = dlo + 32;
    const float* Wr = ps.W[f] + (size_t)o * DH;
    __nv_bfloat16* wh = wh_base + (size_t)f * DH * DH + (size_t)o * DH;
    __nv_bfloat16* wl = wl_base + (size_t)f * DH * DH + (size_t)o * DH;
    float* diag = diag_base + f * 64 * 1024;

    float ss = 0.f;
    for (int j = threadIdx.x; j < dhi; j += blockDim.x) {
        float Wv = Wr[j];
        float w = (j >= dlo) ? expf(Wv) : Wv;
        sw[j] = w;
        ss += w * w;
    }
    #pragma unroll
    for (int off = 16; off; off >>= 1) ss += __shfl_down_sync(0xffffffffu, ss, off);
    if ((threadIdx.x & 31) == 0) red[threadIdx.x >> 5] = ss;
    __syncthreads();
    if (threadIdx.x == 0) {
        float v = 0.f;
        for (int w = 0; w < 8; w++) v += red[w];
        red[0] = v;
    }
    __syncthreads();
    const float scale = expf(ps.dw[f][o]) / sqrtf(red[0]);
    for (int j = threadIdx.x; j < dhi; j += blockDim.x) {
        float v = sw[j] * scale;
        __nv_bfloat16 h, l;
        split_bf16(v, h, l);
        wh[j] = h;
        wl[j] = l;
    }
    if (threadIdx.x < 32)
        diag[bi * 1024 + r * 32 + threadIdx.x] = sw[dlo + threadIdx.x] * scale;
}

// ---------------- prep2 (W2: 64x2048) -> f32 + compact diag, fused ----------------
__global__ void prep2_fused(PtrSet ps, float* __restrict__ wn2_base,
                            float* __restrict__ w2c_base) {
    extern __shared__ float sw[];
    __shared__ float red[8];
    const int f = blockIdx.y;
    const int o = blockIdx.x;            // 0..63
    const int dlo = o * 32, dhi = dlo + 32;
    const float* Wr = ps.W[f] + (size_t)o * DH;
    float* wn = wn2_base + (size_t)f * DIMN * DH + (size_t)o * DH;

    float ss = 0.f;
    for (int j = threadIdx.x; j < DH; j += blockDim.x) {
        float Wv = Wr[j];
        float w = (j >= dhi) ? 0.f : ((j >= dlo) ? expf(Wv) : Wv);
        sw[j] = w;
        ss += w * w;
    }
    #pragma unroll
    for (int off = 16; off; off >>= 1) ss += __shfl_down_sync(0xffffffffu, ss, off);
    if ((threadIdx.x & 31) == 0) red[threadIdx.x >> 5] = ss;
    __syncthreads();
    if (threadIdx.x == 0) {
        float v = 0.f;
        for (int w = 0; w < 8; w++) v += red[w];
        red[0] = v;
    }
    __syncthreads();
    const float scale = expf(ps.dw[f][o]) / sqrtf(red[0]);
    for (int j = threadIdx.x; j < DH; j += blockDim.x) wn[j] = sw[j] * scale;
    if (threadIdx.x < 32)
        w2c_base[f * 2048 + o * 32 + threadIdx.x] = sw[dlo + threadIdx.x] * scale;
}

// ---------------- layer0 GEMM: t1 = tanh(x @ wn0^T + b0), bf16 hi/lo out ------------
__global__ void __launch_bounds__(256)
gemm_l0(const float* __restrict__ A, const float* __restrict__ Bw,
        const float* __restrict__ bias,
        __nv_bfloat16* __restrict__ Th, __nv_bfloat16* __restrict__ Tl) {
    __shared__ float As[16][68];
    __shared__ float Bs[16][68];
    const int tid  = threadIdx.x;
    const int tcol = tid & 15;
    const int trow = tid >> 4;
    const int m0 = blockIdx.y * 64;
    const int nx = 31 - (int)blockIdx.x;    // longest-first
    const int n0 = nx * 64;
    const int keff = 2 * nx + 2;
    const int nk = (keff + 15) >> 4;        // 1..4

    const int rL = tid >> 2;                // 0..63
    const int kL = (tid & 3) * 4;
    const float* pA = A  + (size_t)(m0 + rL) * DIMN + kL;
    const float* pB = Bw + (size_t)(n0 + rL) * DIMN + kL;

    float acc[4][4];
    #pragma unroll
    for (int i = 0; i < 4; i++)
        #pragma unroll
        for (int j = 0; j < 4; j++) acc[i][j] = 0.f;

    for (int t = 0; t < nk; t++) {
        float4 av = *(const float4*)(pA + t * 16);
        float4 bv = *(const float4*)(pB + t * 16);
        As[kL+0][rL] = av.x; As[kL+1][rL] = av.y; As[kL+2][rL] = av.z; As[kL+3][rL] = av.w;
        Bs[kL+0][rL] = bv.x; Bs[kL+1][rL] = bv.y; Bs[kL+2][rL] = bv.z; Bs[kL+3][rL] = bv.w;
        __syncthreads();
        #pragma unroll
        for (int kk = 0; kk < 16; kk++) {
            float4 a = *(const float4*)&As[kk][trow * 4];
            float4 b = *(const float4*)&Bs[kk][tcol * 4];
            acc[0][0] = fmaf(a.x, b.x, acc[0][0]); acc[0][1] = fmaf(a.x, b.y, acc[0][1]);
            acc[0][2] = fmaf(a.x, b.z, acc[0][2]); acc[0][3] = fmaf(a.x, b.w, acc[0][3]);
            acc[1][0] = fmaf(a.y, b.x, acc[1][0]); acc[1][1] = fmaf(a.y, b.y, acc[1][1]);
            acc[1][2] = fmaf(a.y, b.z, acc[1][2]); acc[1][3] = fmaf(a.y, b.w, acc[1][3]);
            acc[2][0] = fmaf(a.z, b.x, acc[2][0]); acc[2][1] = fmaf(a.z, b.y, acc[2][1]);
            acc[2][2] = fmaf(a.z, b.z, acc[2][2]); acc[2][3] = fmaf(a.z, b.w, acc[2][3]);
            acc[3][0] = fmaf(a.w, b.x, acc[3][0]); acc[3][1] = fmaf(a.w, b.y, acc[3][1]);
            acc[3][2] = fmaf(a.w, b.z, acc[3][2]); acc[3][3] = fmaf(a.w, b.w, acc[3][3]);
        }
        __syncthreads();
    }

    const int ncol = n0 + tcol * 4;
    const float4 bv = *(const float4*)&bias[ncol];
    const float bcol[4] = { bv.x, bv.y, bv.z, bv.w };
    #pragma unroll
    for (int i = 0; i < 4; i++) {
        const int m = m0 + trow * 4 + i;
        __nv_bfloat16 hv[4], lv[4];
        #pragma unroll
        for (int c = 0; c < 4; c++) {
            float tv = tanhf(acc[i][c] + bcol[c]);
            split_bf16(tv, hv[c], lv[c]);
        }
        *(uint2*)&Th[(size_t)m * DH + ncol] = *(uint2*)hv;
        *(uint2*)&Tl[(size_t)m * DH + ncol] = *(uint2*)lv;
    }
}

// ---------------- layer1 HMMA GEMM (split-bf16, block-triangular K-early-exit) ----------
// CTA 128(M) x 64(N); grid 256 CTAs. Load-balanced bid->tile map exploiting
// LUT_classic[bid % 148] placement: bid i and i+148 co-reside; 40 singles = bids
// 108..147 get the 40 longest tiles; pairs (i, i+148) get complementary loads.
__global__ void __launch_bounds__(256, 2)
gemm_mma_l1(const __nv_bfloat16* __restrict__ Ah, const __nv_bfloat16* __restrict__ Al,
            const __nv_bfloat16* __restrict__ Bh, const __nv_bfloat16* __restrict__ Bl,
            const float* __restrict__ bias, float* __restrict__ T) {
    extern __shared__ char smem[];
    const int K = DH, N = DH;
    const int tid = threadIdx.x, lane = tid & 31, wid = tid >> 5;
    const int warpM = wid & 1, warpN = wid >> 1;   // 2 x 4 warps, warp tile 64x16
    const int bid = blockIdx.x;
    int s;                                   // rank in longest-first order (0..255)
    if (bid >= 108 && bid < 148)      s = bid - 108;          // singles: 40 longest
    else if (bid < 108)               s = 40 + bid;           // pair member (long)
    else                              s = 255 - (bid - 148);  // pair member (short)
    const int jn = 31 - (s >> 3);
    const int mi = s & 7;
    const int m0 = mi * 128, n0 = jn * 64;
    const int NK = min(64, 2 * jn + 4);
    const uint32_t sbase = smem_u32(smem);

    const __nv_bfloat16* gA[2] = { Ah + (size_t)m0 * K, Al + (size_t)m0 * K };
    const __nv_bfloat16* gB[2] = { Bh + (size_t)n0 * K, Bl + (size_t)n0 * K };

    float acc[4][2][4];
    #pragma unroll
    for (int i = 0; i < 4; i++)
        #pragma unroll
        for (int j = 0; j < 2; j++)
            #pragma unroll
            for (int e = 0; e < 4; e++) acc[i][j][e] = 0.f;

    const int pr_row = tid >> 2;
    const int pr_ch  = tid & 3;
    #define PREFETCH(t) do {                                                          \
        uint32_t stb = sbase + ((t) % 3) * 24576;                                     \
        _Pragma("unroll")                                                             \
        for (int a = 0; a < 2; a++) {                                                 \
            _Pragma("unroll")                                                         \
            for (int j = 0; j < 2; j++) {                                             \
                int row = pr_row + j * 64;                                            \
                const __nv_bfloat16* src = gA[a] + (size_t)row * K + (t) * 32 + pr_ch * 8; \
                uint32_t dst = stb + a * 8192 + row * 64 + ((pr_ch ^ ((row >> 1) & 3)) * 16); \
                cp_async16(dst, src);                                                 \
            }                                                                         \
            const __nv_bfloat16* srcb = gB[a] + (size_t)pr_row * K + (t) * 32 + pr_ch * 8; \
            uint32_t dstb = stb + 16384 + a * 4096 + pr_row * 64                      \
                          + ((pr_ch ^ ((pr_row >> 1) & 3)) * 16);                     \
            cp_async16(dstb, srcb);                                                   \
        }                                                                             \
        cp_commit();                                                                  \
    } while (0)

    PREFETCH(0);
    PREFETCH(1);

    const int rlA = warpM * 64 + (lane & 15);
    const int rlB = warpN * 16 + (lane & 15);
    const int hi  = lane >> 4;
    const int xA  = (rlA >> 1) & 3;
    const int xB  = (rlB >> 1) & 3;

    for (int t = 0; t < NK; t++) {
        if (t + 1 < NK) { CP_WAIT(1); } else { CP_WAIT(0); }
        __syncthreads();
        if (t + 2 < NK) PREFETCH(t + 2);

        const uint32_t stb = sbase + (t % 3) * 24576;
        const uint32_t pAh = stb + rlA * 64;
        const uint32_t pAl = pAh + 8192;
        const uint32_t pBh = stb + 16384 + rlB * 64;
        const uint32_t pBl = pBh + 4096;

        #pragma unroll
        for (int ks = 0; ks < 2; ks++) {
            const uint32_t cA = (uint32_t)(((ks * 2 + hi) ^ xA) * 16);
            const uint32_t cB = (uint32_t)(((ks * 2 + hi) ^ xB) * 16);
            uint32_t ah[4][4], al[4][4], bh[2][2], bl[2][2];
            #pragma unroll
            for (int mt = 0; mt < 4; mt++) {
                LDSM4(ah[mt], pAh + mt * 1024 + cA);
                LDSM4(al[mt], pAl + mt * 1024 + cA);
            }
            {
                uint32_t r[4];
                LDSM4(r, pBh + cB);
                bh[0][0] = r[0]; bh[1][0] = r[1];
                bh[0][1] = r[2]; bh[1][1] = r[3];
                LDSM4(r, pBl + cB);
                bl[0][0] = r[0]; bl[1][0] = r[1];
                bl[0][1] = r[2]; bl[1][1] = r[3];
            }
            #pragma unroll
            for (int mt = 0; mt < 4; mt++)
                #pragma unroll
                for (int nt = 0; nt < 2; nt++) {
                    mma_bf16(acc[mt][nt], ah[mt], bh[nt]);
                    mma_bf16(acc[mt][nt], ah[mt], bl[nt]);
                    mma_bf16(acc[mt][nt], al[mt], bh[nt]);
                }
        }
    }

    const int er = lane >> 2, ec = (lane & 3) * 2;
    #pragma unroll
    for (int nt = 0; nt < 2; nt++) {
        const int col = n0 + warpN * 16 + nt * 8 + ec;
        const float2 bv = *(const float2*)&bias[col];
        #pragma unroll
        for (int mt = 0; mt < 4; mt++) {
            const int r0 = m0 + warpM * 64 + mt * 16 + er;
            float t00 = tanhf(acc[mt][nt][0] + bv.x);
            float t01 = tanhf(acc[mt][nt][1] + bv.y);
            float t10 = tanhf(acc[mt][nt][2] + bv.x);
            float t11 = tanhf(acc[mt][nt][3] + bv.y);
            *(float2*)&T[(size_t)r0 * N + col]       = make_float2(t00, t01);
            *(float2*)&T[(size_t)(r0 + 8) * N + col] = make_float2(t10, t11);
        }
    }
}

// ---------------- layer2 split-K partial GEMM (M=1024, N=64, K=2048) ----------------
__global__ void gemm_l2_partial(const float* __restrict__ A, const float* __restrict__ Bw,
                                float* __restrict__ part) {
    const int BM = 64, BN = 64, BK = 16, TM = 4, TN = 4;
    __shared__ float As[BK][BM];
    __shared__ float Bs[BK][BN];
    const int tid  = threadIdx.x;
    const int tcol = tid % (BN / TN);
    const int trow = tid / (BN / TN);
    const int kp = blockIdx.x;
    const int m0 = blockIdx.y * BM;
    const int kbeg = kp * 256, kend = kbeg + 256;
    const int kmax_thr = (tcol * 4 + 4) * 32;

    float acc[TM][TN];
    #pragma unroll
    for (int i = 0; i < TM; i++)
        #pragma unroll
        for (int j = 0; j < TN; j++) acc[i][j] = 0.f;

    for (int k0 = kbeg; k0 < kend; k0 += BK) {
        #pragma unroll
        for (int idx = tid; idx < BM * BK; idx += 256) {
            int m = idx / BK, kk = idx % BK;
            As[kk][m] = A[(size_t)(m0 + m) * DH + k0 + kk];
        }
        #pragma unroll
        for (int idx = tid; idx < BN * BK; idx += 256) {
            int n = idx / BK, kk = idx % BK;
            Bs[kk][n] = Bw[(size_t)n * DH + k0 + kk];
        }
        __syncthreads();
        if (k0 < kmax_thr) {
            #pragma unroll
            for (int kk = 0; kk < BK; kk++) {
                float ar[TM], br[TN];
                #pragma unroll
                for (int i = 0; i < TM; i++) ar[i] = As[kk][trow * TM + i];
                #pragma unroll
                for (int j = 0; j < TN; j++) br[j] = Bs[kk][tcol * TN + j];
                #pragma unroll
                for (int i = 0; i < TM; i++)
                    #pragma unroll
                    for (int j = 0; j < TN; j++)
                        acc[i][j] = fmaf(ar[i], br[j], acc[i][j]);
            }
        }
        __syncthreads();
    }
    #pragma unroll
    for (int i = 0; i < TM; i++) {
        int m = m0 + trow * TM + i;
        #pragma unroll
        for (int j = 0; j < TN; j++) {
            int n = tcol * TN + j;
            part[(size_t)kp * BATCH * DIMN + (size_t)m * DIMN + n] = acc[i][j];
        }
    }
}

// ---------------- Jacobian chain (linear domain, d recomputed from t) ----------------
__global__ void __launch_bounds__(256)
grad_kernel(const float* __restrict__ w1d, const float* __restrict__ v0c,
            const float* __restrict__ w2c,
            const __nv_bfloat16* __restrict__ t1h, const __nv_bfloat16* __restrict__ t1l,
            const float* __restrict__ t2,
            const float* __restrict__ gate, int use_gate,
            float* __restrict__ ldjc) {
    __shared__ float s_w1[HID][HID + 1];
    __shared__ float s_v0[HID];
    __shared__ float s_w2[HID];
    const int i = blockIdx.x;
    const int tid = threadIdx.x;
    for (int idx = tid; idx < HID * HID; idx += 256) {
        int r = idx >> 5, c = idx & 31;
        s_w1[r][c] = w1d[i * 1024 + r * 32 + c];
    }
    if (tid < HID) {
        s_v0[tid] = v0c[i * 32 + tid];
        s_w2[tid] = w2c[i * 32 + tid];
    }
    __syncthreads();
    const int warp = tid >> 5, lane = tid & 31;
    const int b = blockIdx.y * 8 + warp;
    const size_t off = (size_t)b * DH + i * HID + lane;

    float t1v = __bfloat162float(t1h[off]) + __bfloat162float(t1l[off]);
    float u1 = s_v0[lane] * (1.f - t1v * t1v);
    float acc = 0.f;
    #pragma unroll
    for (int k = 0; k < HID; k++) {
        float uk = __shfl_sync(0xffffffffu, u1, k);
        acc = fmaf(s_w1[lane][k], uk, acc);
    }
    float t2v = t2[off];
    float term = s_w2[lane] * acc * (1.f - t2v * t2v);
    #pragma unroll
    for (int o = 16; o; o >>= 1) term += __shfl_down_sync(0xffffffffu, term, o);
    if (lane == 0) {
        float c;
        if (use_gate) {
            float g = gate[0];
            c = log1pf(term * expf(g)) - log1pf(expf(g));
        } else {
            c = logf(term);
        }
        ldjc[(size_t)b * DIMN + i] = c;
    }
}

// ---------------- fused split-K reduce + gate mix + reversal + ldj / final ----------
__global__ void __launch_bounds__(256)
mix_kernel(const float* __restrict__ part, const float* __restrict__ b2,
           const float* __restrict__ ldjc, const float* __restrict__ gate,
           int flow, const float* __restrict__ xin, float* __restrict__ xout,
           float* __restrict__ ldj, float* __restrict__ outf) {
    const int warp = threadIdx.x >> 5, lane = threadIdx.x & 31;
    const int b = blockIdx.x * 8 + warp;

    float sum = ldjc[(size_t)b * DIMN + lane] + ldjc[(size_t)b * DIMN + 32 + lane];

    float h0 = b2[lane], h1 = b2[lane + 32];
    #pragma unroll
    for (int kp = 0; kp < 8; kp++) {
        h0 += part[(size_t)kp * BATCH * DIMN + b * 64 + lane];
        h1 += part[(size_t)kp * BATCH * DIMN + b * 64 + 32 + lane];
    }

    if (flow < 2) {
        float gv = gate[0];
        float s = 1.f / (1.f + expf(-gv));
        float o0 = s * h0 + (1.f - s) * xin[b * 64 + lane];
        float o1 = s * h1 + (1.f - s) * xin[b * 64 + 32 + lane];
        xout[b * 64 + 63 - lane] = o0;   // reversal
        xout[b * 64 + 31 - lane] = o1;
        #pragma unroll
        for (int o = 16; o; o >>= 1) sum += __shfl_down_sync(0xffffffffu, sum, o);
        if (lane == 0) {
            if (flow == 0) ldj[b] = sum;
            else           ldj[b] += sum;
        }
    } else {
        sum += -0.5f * (h0 * h0 + h1 * h1) - LOG2PI_F;
        #pragma unroll
        for (int o = 16; o; o >>= 1) sum += __shfl_down_sync(0xffffffffu, sum, o);
        if (lane == 0) outf[b] = ldj[b] + sum;
    }
}

// ---------------- launch ----------------
extern "C" void kernel_launch(void* const* d_in, const int* in_sizes, int n_in,
                              void* d_out, int out_size) {
    const float* x = (const float*)d_in[0];
    const float* gates[2] = { (const float*)d_in[28], (const float*)d_in[29] };

    float *wn0, *wn2, *t2, *xa, *xb, *ldj, *ldjc, *part, *w1d, *v0c, *w2c;
    __nv_bfloat16 *w1h, *w1l, *t1h, *t1l;
    cudaGetSymbolAddress((void**)&wn0,  g_wn0);
    cudaGetSymbolAddress((void**)&wn2,  g_wn2);
    cudaGetSymbolAddress((void**)&w1h,  g_w1h);
    cudaGetSymbolAddress((void**)&w1l,  g_w1l);
    cudaGetSymbolAddress((void**)&w1d,  g_w1d);
    cudaGetSymbolAddress((void**)&v0c,  g_v0c);
    cudaGetSymbolAddress((void**)&w2c,  g_w2c);
    cudaGetSymbolAddress((void**)&t1h,  g_t1h);
    cudaGetSymbolAddress((void**)&t1l,  g_t1l);
    cudaGetSymbolAddress((void**)&t2,   g_t2);
    cudaGetSymbolAddress((void**)&xa,   g_xa);
    cudaGetSymbolAddress((void**)&xb,   g_xb);
    cudaGetSymbolAddress((void**)&ldj,  g_ldj);
    cudaGetSymbolAddress((void**)&ldjc, g_ldjc);
    cudaGetSymbolAddress((void**)&part, g_part);

    const size_t SZ1 = (size_t)DH * DH;

    const int DYN_SMEM = 3 * 24576;
    cudaFuncSetAttribute(gemm_mma_l1, cudaFuncAttributeMaxDynamicSharedMemorySize, DYN_SMEM);

    PtrSet p0, p1, p2;
    for (int f = 0; f < 3; f++) {
        p0.W[f]  = (const float*)d_in[1 + f * 9 + 0];
        p0.dw[f] = (const float*)d_in[1 + f * 9 + 1];
        p1.W[f]  = (const float*)d_in[1 + f * 9 + 3];
        p1.dw[f] = (const float*)d_in[1 + f * 9 + 4];
        p2.W[f]  = (const float*)d_in[1 + f * 9 + 6];
        p2.dw[f] = (const float*)d_in[1 + f * 9 + 7];
    }
    prep0_fused<<<dim3(256, 3),  256>>>(p0, wn0, v0c);
    prep1_fused<<<dim3(DH, 3),   256, DH * sizeof(float)>>>(p1, w1h, w1l, w1d);
    prep2_fused<<<dim3(DIMN, 3), 256, DH * sizeof(float)>>>(p2, wn2, w2c);

    const float* xcur = x;
    for (int f = 0; f < 3; f++) {
        const float* b0 = (const float*)d_in[1 + f * 9 + 2];
        const float* b1 = (const float*)d_in[1 + f * 9 + 5];
        const float* b2 = (const float*)d_in[1 + f * 9 + 8];

        gemm_l0<<<dim3(32, 16), 256>>>(xcur, wn0 + (size_t)f * DH * DIMN, b0, t1h, t1l);
        gemm_mma_l1<<<256, 256, DYN_SMEM>>>(
            t1h, t1l, w1h + f * SZ1, w1l + f * SZ1, b1, t2);
        gemm_l2_partial<<<dim3(8, 16), 256>>>(t2, wn2 + (size_t)f * DIMN * DH, part);

        grad_kernel<<<dim3(DIMN, BATCH / 8), 256>>>(
            w1d + f * 64 * 1024, v0c + f * 2048, w2c + f * 2048,
            t1h, t1l, t2,
            (f < 2) ? gates[f] : nullptr, (f < 2) ? 1 : 0, ldjc);

        float* xnext = (f == 0) ? xa : xb;
        mix_kernel<<<128, 256>>>(
            part, b2, ldjc, (f < 2) ? gates[f] : nullptr, f,
            xcur, xnext, ldj, (float*)d_out);
        xcur = xnext;
    }
}